// round 12
// baseline (speedup 1.0000x reference)
#include <cuda_runtime.h>
#include <cuda_fp16.h>
#include <cuda_bf16.h>
#include <cstdint>

#define NC  100000
#define NT  100000
#define NNZ 640000
#define D   128
#define CAP 16           // bucket capacity (P(n>16)~3e-4 -> inline overflow)

#define PREP_BLOCKS 1184                    // full wave (8 blocks/SM x 148)
#define PREP_T      256
#define ROLE_THREADS (PREP_BLOCKS * 128)    // 151552 threads per role
#define CONV_UNITS  (NT * D / 8)            // 1.6M uint4 units (8 halves each)

// ---- device-global scratch (no allocation allowed) ----
// g_meta[0] = overflow count; g_meta[1..NC] = per-row nnz counts.
__device__ int   g_meta[NC + 1];
__device__ int   g_bucket[NC * CAP];   // col indices bucketed by row (6.4 MB)
__device__ int2  g_ovf[NNZ];           // overflow (row,col) pairs (worst case)
__device__ uint4 g_half[NT * D / 8];   // fp16 copy of mat (25.6 MB)

__device__ __forceinline__ __half2 u2h(unsigned u) {
    return *reinterpret_cast<__half2*>(&u);
}

__device__ __forceinline__ uint4 cvt8(float4 a, float4 b) {
    __half2 h0 = __float22half2_rn(make_float2(a.x, a.y));
    __half2 h1 = __float22half2_rn(make_float2(a.z, a.w));
    __half2 h2 = __float22half2_rn(make_float2(b.x, b.y));
    __half2 h3 = __float22half2_rn(make_float2(b.z, b.w));
    uint4 u;
    u.x = *reinterpret_cast<unsigned*>(&h0);
    u.y = *reinterpret_cast<unsigned*>(&h1);
    u.z = *reinterpret_cast<unsigned*>(&h2);
    u.w = *reinterpret_cast<unsigned*>(&h3);
    return u;
}

// Phase 1: warp-split roles, full wave. Bucket warps: 5-deep batched
// atomic/store chains. Convert warps: 2-deep batched, mat read with __ldcs
// (evict-first) so the one-shot 51MB stream does NOT evict g_half/g_bucket
// from L2 — they must stay resident for the gather phase.
__global__ __launch_bounds__(PREP_T) void prep_kernel(
    const int*    __restrict__ row,
    const int*    __restrict__ col,
    const float4* __restrict__ matf4) {
    const int wid  = threadIdx.x >> 5;
    const int lane = threadIdx.x & 31;

    if (wid < 4) {
        // ---- bucket role: up to 5 entries per thread, batched ----
        int* cnt = g_meta + 1;
        const int idx = blockIdx.x * 128 + wid * 32 + lane;

        int r[5], c[5], slot[5];
        bool ok[5];
        #pragma unroll
        for (int k = 0; k < 5; ++k) {
            int i = idx + k * ROLE_THREADS;
            ok[k] = (i < NNZ);
            if (ok[k]) { r[k] = __ldg(row + i); c[k] = __ldg(col + i); }
        }
        #pragma unroll
        for (int k = 0; k < 5; ++k)
            if (ok[k]) slot[k] = atomicAdd(&cnt[r[k]], 1);
        #pragma unroll
        for (int k = 0; k < 5; ++k) {
            if (ok[k]) {
                if (slot[k] < CAP) {
                    g_bucket[r[k] * CAP + slot[k]] = c[k];
                } else {
                    int p = atomicAdd(&g_meta[0], 1);
                    g_ovf[p] = make_int2(r[k], c[k]);
                }
            }
        }
    } else {
        // ---- convert role: 2-deep batched streaming ----
        const int idx = blockIdx.x * 128 + (wid - 4) * 32 + lane;
        int p = idx;
        for (; p + ROLE_THREADS < CONV_UNITS; p += 2 * ROLE_THREADS) {
            int p2 = p + ROLE_THREADS;
            float4 a0 = __ldcs(matf4 + 2 * p);
            float4 b0 = __ldcs(matf4 + 2 * p + 1);
            float4 a1 = __ldcs(matf4 + 2 * p2);
            float4 b1 = __ldcs(matf4 + 2 * p2 + 1);
            g_half[p]  = cvt8(a0, b0);
            g_half[p2] = cvt8(a1, b1);
        }
        if (p < CONV_UNITS) {
            float4 a = __ldcs(matf4 + 2 * p);
            float4 b = __ldcs(matf4 + 2 * p + 1);
            g_half[p] = cvt8(a, b);
        }
    }
}

// Phase 2: HALF-WARP per row (measured best). One fp16 row = 256 B =
// 16 lanes x uint4 (LDG.128). Predicated zero-filled batches of 4, depth-2
// HADD2 tree -> fp32 accumulate. Out written with __stcs (evict-first; out
// is never re-read — keep it from displacing g_half in L2).
__global__ __launch_bounds__(256) void gather_sum_kernel(
    float4* __restrict__ out) {
    const int gw   = (blockIdx.x * blockDim.x + threadIdx.x) >> 5;
    const int lane = threadIdx.x & 31;
    const int half = lane >> 4;
    const int lh   = lane & 15;
    const int r    = gw * 2 + half;
    if (r >= NC) return;                // NC even: whole warp exits together

    const int*   cnt   = g_meta + 1;
    const uint4* rows4 = g_half;

    int cj = __ldg(g_bucket + r * CAP + lh);
    int nr = __ldg(cnt + r);
    int n  = nr > CAP ? CAP : nr;

    float acc[8] = {0.f, 0.f, 0.f, 0.f, 0.f, 0.f, 0.f, 0.f};

    uint4 v[4];
    #pragma unroll
    for (int b = 0; b < 2; ++b) {       // slots 0-3, 4-7 (always)
        #pragma unroll
        for (int j = 0; j < 4; ++j) {
            int s = b * 4 + j;
            int c = __shfl_sync(0xffffffffu, cj, half * 16 + s);
            uint4 t = make_uint4(0u, 0u, 0u, 0u);
            if (s < n) t = __ldg(rows4 + (size_t)c * 16 + lh);
            v[j] = t;
        }
        #pragma unroll
        for (int k = 0; k < 4; ++k) {
            unsigned* c0 = &v[0].x; unsigned* c1 = &v[1].x;
            unsigned* c2 = &v[2].x; unsigned* c3 = &v[3].x;
            __half2 s0 = __hadd2(u2h(c0[k]), u2h(c1[k]));
            __half2 s1 = __hadd2(u2h(c2[k]), u2h(c3[k]));
            float2 f = __half22float2(__hadd2(s0, s1));
            acc[2*k]   += f.x;
            acc[2*k+1] += f.y;
        }
    }

    if (__any_sync(0xffffffffu, n > 8)) {
        #pragma unroll
        for (int b = 2; b < 4; ++b) {   // slots 8-11, 12-15
            #pragma unroll
            for (int j = 0; j < 4; ++j) {
                int s = b * 4 + j;
                int c = __shfl_sync(0xffffffffu, cj, half * 16 + s);
                uint4 t = make_uint4(0u, 0u, 0u, 0u);
                if (s < n) t = __ldg(rows4 + (size_t)c * 16 + lh);
                v[j] = t;
            }
            #pragma unroll
            for (int k = 0; k < 4; ++k) {
                unsigned* c0 = &v[0].x; unsigned* c1 = &v[1].x;
                unsigned* c2 = &v[2].x; unsigned* c3 = &v[3].x;
                __half2 s0 = __hadd2(u2h(c0[k]), u2h(c1[k]));
                __half2 s1 = __hadd2(u2h(c2[k]), u2h(c3[k]));
                float2 f = __half22float2(__hadd2(s0, s1));
                acc[2*k]   += f.x;
                acc[2*k+1] += f.y;
            }
        }
    }

    if (__any_sync(0xffffffffu, nr > CAP)) {
        int ovfn = __ldg(&g_meta[0]);
        for (int i = 0; i < ovfn; ++i) {
            int2 e = __ldg(g_ovf + i);
            if (e.x == r) {
                uint4 h = __ldg(rows4 + (size_t)e.y * 16 + lh);
                float2 f0 = __half22float2(u2h(h.x));
                float2 f1 = __half22float2(u2h(h.y));
                float2 f2 = __half22float2(u2h(h.z));
                float2 f3 = __half22float2(u2h(h.w));
                acc[0] += f0.x; acc[1] += f0.y;
                acc[2] += f1.x; acc[3] += f1.y;
                acc[4] += f2.x; acc[5] += f2.y;
                acc[6] += f3.x; acc[7] += f3.y;
            }
        }
    }

    size_t base = (size_t)r * 32 + lh * 2;
    __stcs(out + base,     make_float4(acc[0], acc[1], acc[2], acc[3]));
    __stcs(out + base + 1, make_float4(acc[4], acc[5], acc[6], acc[7]));
}

extern "C" void kernel_launch(void* const* d_in, const int* in_sizes, int n_in,
                              void* d_out, int out_size) {
    const float4* mat = (const float4*)d_in[0];
    const int*    row = (const int*)d_in[1];
    const int*    col = (const int*)d_in[2];
    float4*       out = (float4*)d_out;

    void* meta_ptr = nullptr;
    cudaGetSymbolAddress(&meta_ptr, g_meta);
    cudaMemsetAsync(meta_ptr, 0, (size_t)(NC + 1) * sizeof(int));

    prep_kernel<<<PREP_BLOCKS, PREP_T>>>(row, col, mat);

    // 50000 warps (2 rows each) = 1.6M threads / 256 = 6250 blocks.
    gather_sum_kernel<<<6250, 256>>>(out);
}

// round 13
// speedup vs baseline: 1.2327x; 1.2327x over previous
#include <cuda_runtime.h>
#include <cuda_fp16.h>
#include <cuda_bf16.h>
#include <cstdint>

#define NC  100000
#define NT  100000
#define NNZ 640000
#define D   128
#define CAP 16           // bucket capacity (P(n>16)~3e-4 -> inline overflow)

#define PREP_BLOCKS 1184                    // full wave (8 blocks/SM x 148)
#define PREP_T      256
#define ROLE_THREADS (PREP_BLOCKS * 128)    // threads per role
#define CONV_UNITS  (NT * D / 8)            // 1.6M uint4 units (8 halves each)

#define GATHER_BLOCKS 1184
#define GATHER_T      256
#define NPAIRS        (NC / 2)              // 50000 row-pairs
#define NWARPS        (GATHER_BLOCKS * GATHER_T / 32)  // 9472

// ---- device-global scratch (no allocation allowed) ----
// g_meta[0] = overflow count; g_meta[1..NC] = per-row nnz counts.
__device__ int   g_meta[NC + 1];
__device__ int   g_bucket[NC * CAP];   // col indices bucketed by row (6.4 MB)
__device__ int2  g_ovf[NNZ];           // overflow (row,col) pairs (worst case)
__device__ uint4 g_half[NT * D / 8];   // fp16 copy of mat (25.6 MB)

__device__ __forceinline__ __half2 u2h(unsigned u) {
    return *reinterpret_cast<__half2*>(&u);
}

// Phase 1: warp-split roles (R11 exact config — measured best; R12's
// batching and __ldcs both regressed). Warps 0-3 bucket, warps 4-7 convert.
__global__ __launch_bounds__(PREP_T) void prep_kernel(
    const int*    __restrict__ row,
    const int*    __restrict__ col,
    const float4* __restrict__ matf4) {
    const int wid  = threadIdx.x >> 5;
    const int lane = threadIdx.x & 31;

    if (wid < 4) {
        int* cnt = g_meta + 1;
        int idx = blockIdx.x * 128 + wid * 32 + lane;
        for (int i = idx; i < NNZ; i += ROLE_THREADS) {
            int r = __ldg(row + i);
            int c = __ldg(col + i);
            int slot = atomicAdd(&cnt[r], 1);
            if (slot < CAP) {
                g_bucket[r * CAP + slot] = c;
            } else {
                int p = atomicAdd(&g_meta[0], 1);
                g_ovf[p] = make_int2(r, c);
            }
        }
    } else {
        int idx = blockIdx.x * 128 + (wid - 4) * 32 + lane;
        for (int p = idx; p < CONV_UNITS; p += ROLE_THREADS) {
            float4 a = __ldg(matf4 + 2 * p);
            float4 b = __ldg(matf4 + 2 * p + 1);
            __half2 h0 = __float22half2_rn(make_float2(a.x, a.y));
            __half2 h1 = __float22half2_rn(make_float2(a.z, a.w));
            __half2 h2 = __float22half2_rn(make_float2(b.x, b.y));
            __half2 h3 = __float22half2_rn(make_float2(b.z, b.w));
            uint4 u;
            u.x = *reinterpret_cast<unsigned*>(&h0);
            u.y = *reinterpret_cast<unsigned*>(&h1);
            u.z = *reinterpret_cast<unsigned*>(&h2);
            u.w = *reinterpret_cast<unsigned*>(&h3);
            g_half[p] = u;
        }
    }
}

// Process one row-pair given already-loaded metadata (cj, nr).
// HALF-WARP per row, predicated zero-filled uint4 batches, depth-2 HADD2
// tree -> fp32 accumulate, plain float4 stores.
__device__ __forceinline__ void process_pair(
    int pair, int half, int lh, int cj, int nr, float4* __restrict__ out) {
    const int r = pair * 2 + half;
    const uint4* rows4 = g_half;
    int n = nr > CAP ? CAP : nr;

    float acc[8] = {0.f, 0.f, 0.f, 0.f, 0.f, 0.f, 0.f, 0.f};
    uint4 v[4];

    #pragma unroll
    for (int b = 0; b < 2; ++b) {       // slots 0-3, 4-7 (always)
        #pragma unroll
        for (int j = 0; j < 4; ++j) {
            int s = b * 4 + j;
            int c = __shfl_sync(0xffffffffu, cj, half * 16 + s);
            uint4 t = make_uint4(0u, 0u, 0u, 0u);
            if (s < n) t = __ldg(rows4 + (size_t)c * 16 + lh);
            v[j] = t;
        }
        #pragma unroll
        for (int k = 0; k < 4; ++k) {
            unsigned* c0 = &v[0].x; unsigned* c1 = &v[1].x;
            unsigned* c2 = &v[2].x; unsigned* c3 = &v[3].x;
            __half2 s0 = __hadd2(u2h(c0[k]), u2h(c1[k]));
            __half2 s1 = __hadd2(u2h(c2[k]), u2h(c3[k]));
            float2 f = __half22float2(__hadd2(s0, s1));
            acc[2*k]   += f.x;
            acc[2*k+1] += f.y;
        }
    }

    if (__any_sync(0xffffffffu, n > 8)) {
        #pragma unroll
        for (int b = 2; b < 4; ++b) {   // slots 8-11, 12-15
            #pragma unroll
            for (int j = 0; j < 4; ++j) {
                int s = b * 4 + j;
                int c = __shfl_sync(0xffffffffu, cj, half * 16 + s);
                uint4 t = make_uint4(0u, 0u, 0u, 0u);
                if (s < n) t = __ldg(rows4 + (size_t)c * 16 + lh);
                v[j] = t;
            }
            #pragma unroll
            for (int k = 0; k < 4; ++k) {
                unsigned* c0 = &v[0].x; unsigned* c1 = &v[1].x;
                unsigned* c2 = &v[2].x; unsigned* c3 = &v[3].x;
                __half2 s0 = __hadd2(u2h(c0[k]), u2h(c1[k]));
                __half2 s1 = __hadd2(u2h(c2[k]), u2h(c3[k]));
                float2 f = __half22float2(__hadd2(s0, s1));
                acc[2*k]   += f.x;
                acc[2*k+1] += f.y;
            }
        }
    }

    if (__any_sync(0xffffffffu, nr > CAP)) {
        int ovfn = __ldg(&g_meta[0]);
        for (int i = 0; i < ovfn; ++i) {
            int2 e = __ldg(g_ovf + i);
            if (e.x == r) {
                uint4 h = __ldg(rows4 + (size_t)e.y * 16 + lh);
                float2 f0 = __half22float2(u2h(h.x));
                float2 f1 = __half22float2(u2h(h.y));
                float2 f2 = __half22float2(u2h(h.z));
                float2 f3 = __half22float2(u2h(h.w));
                acc[0] += f0.x; acc[1] += f0.y;
                acc[2] += f1.x; acc[3] += f1.y;
                acc[4] += f2.x; acc[5] += f2.y;
                acc[6] += f3.x; acc[7] += f3.y;
            }
        }
    }

    size_t base = (size_t)r * 32 + lh * 2;
    out[base]     = make_float4(acc[0], acc[1], acc[2], acc[3]);
    out[base + 1] = make_float4(acc[4], acc[5], acc[6], acc[7]);
}

// Phase 2: persistent gather, software-pipelined. Each warp grid-strides
// over ~5-6 row-pairs; the NEXT pair's bucket line + count are loaded BEFORE
// processing the current pair, hiding the meta->row-load dependency chain
// (the single-shot version stalled 59% of cycles on exactly that chain).
__global__ __launch_bounds__(GATHER_T) void gather_sum_kernel(
    float4* __restrict__ out) {
    const int gwarp = (blockIdx.x * GATHER_T + threadIdx.x) >> 5;
    const int lane  = threadIdx.x & 31;
    const int half  = lane >> 4;
    const int lh    = lane & 15;

    const int* cnt = g_meta + 1;

    int pair = gwarp;
    if (pair >= NPAIRS) return;

    // Prologue: load metadata for the first pair.
    int r  = pair * 2 + half;
    int cj = __ldg(g_bucket + r * CAP + lh);
    int nr = __ldg(cnt + r);

    while (true) {
        int next = pair + NWARPS;
        int cj_n = 0, nr_n = 0;
        if (next < NPAIRS) {
            int rn = next * 2 + half;
            cj_n = __ldg(g_bucket + rn * CAP + lh);   // in flight during compute
            nr_n = __ldg(cnt + rn);
        }

        process_pair(pair, half, lh, cj, nr, out);

        if (next >= NPAIRS) break;
        pair = next;
        cj = cj_n;
        nr = nr_n;
    }
}

extern "C" void kernel_launch(void* const* d_in, const int* in_sizes, int n_in,
                              void* d_out, int out_size) {
    const float4* mat = (const float4*)d_in[0];
    const int*    row = (const int*)d_in[1];
    const int*    col = (const int*)d_in[2];
    float4*       out = (float4*)d_out;

    void* meta_ptr = nullptr;
    cudaGetSymbolAddress(&meta_ptr, g_meta);
    cudaMemsetAsync(meta_ptr, 0, (size_t)(NC + 1) * sizeof(int));

    prep_kernel<<<PREP_BLOCKS, PREP_T>>>(row, col, mat);

    gather_sum_kernel<<<GATHER_BLOCKS, GATHER_T>>>(out);
}

// round 14
// speedup vs baseline: 1.3360x; 1.0838x over previous
#include <cuda_runtime.h>
#include <cuda_fp16.h>
#include <cuda_bf16.h>
#include <cstdint>

#define NC  100000
#define NT  100000
#define NNZ 640000
#define D   128
#define CAP 16           // bucket capacity (P(n>16)~3e-4 -> inline overflow)

#define CONV_UNITS  (NT * D / 8)   // 1.6M uint4 units (8 halves each)

// ---- device-global scratch (no allocation allowed) ----
// g_meta[0] = overflow count; g_meta[1..NC] = per-row nnz counts.
__device__ int   g_meta[NC + 1];
__device__ int   g_bucket[NC * CAP];   // col indices bucketed by row (6.4 MB)
__device__ int2  g_ovf[NNZ];           // overflow (row,col) pairs (worst case)
__device__ uint4 g_half[NT * D / 8];   // fp16 copy of mat (25.6 MB)

__device__ __forceinline__ __half2 u2h(unsigned u) {
    return *reinterpret_cast<__half2*>(&u);
}

// Branch A: bucket the nonzeros (measured-best shape: 2500 blocks, R3 =
// 12.6us). Bound by LSU/L2 scattered-transaction throughput.
__global__ __launch_bounds__(256) void bucket_kernel(
    const int* __restrict__ row, const int* __restrict__ col) {
    int i = blockIdx.x * blockDim.x + threadIdx.x;
    if (i >= NNZ) return;
    int* cnt = g_meta + 1;
    int r = __ldg(row + i);
    int c = __ldg(col + i);
    int slot = atomicAdd(&cnt[r], 1);
    if (slot < CAP) {
        g_bucket[r * CAP + slot] = c;
    } else {
        int p = atomicAdd(&g_meta[0], 1);
        g_ovf[p] = make_int2(r, c);
    }
}

// Branch B: stream-convert mat fp32 -> fp16 (DRAM-bound). Runs CONCURRENTLY
// with bucket_kernel as a parallel graph branch.
__global__ __launch_bounds__(256) void convert_kernel(
    const float4* __restrict__ matf4) {
    const int stride = gridDim.x * blockDim.x;
    for (int p = blockIdx.x * blockDim.x + threadIdx.x; p < CONV_UNITS; p += stride) {
        float4 a = __ldg(matf4 + 2 * p);
        float4 b = __ldg(matf4 + 2 * p + 1);
        __half2 h0 = __float22half2_rn(make_float2(a.x, a.y));
        __half2 h1 = __float22half2_rn(make_float2(a.z, a.w));
        __half2 h2 = __float22half2_rn(make_float2(b.x, b.y));
        __half2 h3 = __float22half2_rn(make_float2(b.z, b.w));
        uint4 u;
        u.x = *reinterpret_cast<unsigned*>(&h0);
        u.y = *reinterpret_cast<unsigned*>(&h1);
        u.z = *reinterpret_cast<unsigned*>(&h2);
        u.w = *reinterpret_cast<unsigned*>(&h3);
        g_half[p] = u;
    }
}

// Phase 2: R11-exact gather (measured best 24.2us). HALF-WARP per row:
// one fp16 row = 256 B = 16 lanes x uint4 (LDG.128). Predicated zero-filled
// batches of 4, depth-2 HADD2 tree -> fp32 accumulate, plain float4 stores.
__global__ __launch_bounds__(256) void gather_sum_kernel(
    float4* __restrict__ out) {
    const int gw   = (blockIdx.x * blockDim.x + threadIdx.x) >> 5;
    const int lane = threadIdx.x & 31;
    const int half = lane >> 4;
    const int lh   = lane & 15;
    const int r    = gw * 2 + half;
    if (r >= NC) return;                // NC even: whole warp exits together

    const int*   cnt   = g_meta + 1;
    const uint4* rows4 = g_half;

    int cj = __ldg(g_bucket + r * CAP + lh);
    int nr = __ldg(cnt + r);
    int n  = nr > CAP ? CAP : nr;

    float acc[8] = {0.f, 0.f, 0.f, 0.f, 0.f, 0.f, 0.f, 0.f};

    uint4 v[4];
    #pragma unroll
    for (int b = 0; b < 2; ++b) {       // slots 0-3, 4-7 (always)
        #pragma unroll
        for (int j = 0; j < 4; ++j) {
            int s = b * 4 + j;
            int c = __shfl_sync(0xffffffffu, cj, half * 16 + s);
            uint4 t = make_uint4(0u, 0u, 0u, 0u);
            if (s < n) t = __ldg(rows4 + (size_t)c * 16 + lh);
            v[j] = t;
        }
        #pragma unroll
        for (int k = 0; k < 4; ++k) {
            unsigned* c0 = &v[0].x; unsigned* c1 = &v[1].x;
            unsigned* c2 = &v[2].x; unsigned* c3 = &v[3].x;
            __half2 s0 = __hadd2(u2h(c0[k]), u2h(c1[k]));
            __half2 s1 = __hadd2(u2h(c2[k]), u2h(c3[k]));
            float2 f = __half22float2(__hadd2(s0, s1));
            acc[2*k]   += f.x;
            acc[2*k+1] += f.y;
        }
    }

    if (__any_sync(0xffffffffu, n > 8)) {
        #pragma unroll
        for (int b = 2; b < 4; ++b) {   // slots 8-11, 12-15
            #pragma unroll
            for (int j = 0; j < 4; ++j) {
                int s = b * 4 + j;
                int c = __shfl_sync(0xffffffffu, cj, half * 16 + s);
                uint4 t = make_uint4(0u, 0u, 0u, 0u);
                if (s < n) t = __ldg(rows4 + (size_t)c * 16 + lh);
                v[j] = t;
            }
            #pragma unroll
            for (int k = 0; k < 4; ++k) {
                unsigned* c0 = &v[0].x; unsigned* c1 = &v[1].x;
                unsigned* c2 = &v[2].x; unsigned* c3 = &v[3].x;
                __half2 s0 = __hadd2(u2h(c0[k]), u2h(c1[k]));
                __half2 s1 = __hadd2(u2h(c2[k]), u2h(c3[k]));
                float2 f = __half22float2(__hadd2(s0, s1));
                acc[2*k]   += f.x;
                acc[2*k+1] += f.y;
            }
        }
    }

    if (__any_sync(0xffffffffu, nr > CAP)) {
        int ovfn = __ldg(&g_meta[0]);
        for (int i = 0; i < ovfn; ++i) {
            int2 e = __ldg(g_ovf + i);
            if (e.x == r) {
                uint4 h = __ldg(rows4 + (size_t)e.y * 16 + lh);
                float2 f0 = __half22float2(u2h(h.x));
                float2 f1 = __half22float2(u2h(h.y));
                float2 f2 = __half22float2(u2h(h.z));
                float2 f3 = __half22float2(u2h(h.w));
                acc[0] += f0.x; acc[1] += f0.y;
                acc[2] += f1.x; acc[3] += f1.y;
                acc[4] += f2.x; acc[5] += f2.y;
                acc[6] += f3.x; acc[7] += f3.y;
            }
        }
    }

    size_t base = (size_t)r * 32 + lh * 2;
    out[base]     = make_float4(acc[0], acc[1], acc[2], acc[3]);
    out[base + 1] = make_float4(acc[4], acc[5], acc[6], acc[7]);
}

extern "C" void kernel_launch(void* const* d_in, const int* in_sizes, int n_in,
                              void* d_out, int out_size) {
    const float4* mat = (const float4*)d_in[0];
    const int*    row = (const int*)d_in[1];
    const int*    col = (const int*)d_in[2];
    float4*       out = (float4*)d_out;

    // Lazily create a side stream + events (host objects only, no device
    // memory; created on the first, non-captured call). During graph capture
    // the record/wait pair forks a parallel branch so bucket_kernel and
    // convert_kernel run CONCURRENTLY — they contend for the same LSU pipe
    // when co-resident in one kernel (every intra-kernel split measured
    // 20.5-23.5us) but are bound by different resources as separate kernels.
    static cudaStream_t s2 = nullptr;
    static cudaEvent_t  evFork = nullptr, evJoin = nullptr;
    if (s2 == nullptr) {
        cudaStreamCreateWithFlags(&s2, cudaStreamNonBlocking);
        cudaEventCreateWithFlags(&evFork, cudaEventDisableTiming);
        cudaEventCreateWithFlags(&evJoin, cudaEventDisableTiming);
    }

    void* meta_ptr = nullptr;
    cudaGetSymbolAddress(&meta_ptr, g_meta);
    cudaMemsetAsync(meta_ptr, 0, (size_t)(NC + 1) * sizeof(int));

    // Fork: convert on s2, bucket on the main stream.
    cudaEventRecord(evFork, 0);
    cudaStreamWaitEvent(s2, evFork, 0);
    convert_kernel<<<1184, 256, 0, s2>>>(mat);

    bucket_kernel<<<(NNZ + 255) / 256, 256>>>(row, col);   // 2500 blocks

    // Join: gather needs both branches complete.
    cudaEventRecord(evJoin, s2);
    cudaStreamWaitEvent(0, evJoin, 0);

    // 50000 warps (2 rows each) = 1.6M threads / 256 = 6250 blocks.
    gather_sum_kernel<<<6250, 256>>>(out);
}